// round 16
// baseline (speedup 1.0000x reference)
#include <cuda_runtime.h>
#include <cuda_bf16.h>
#include <cuda_fp16.h>
#include <cstdint>

#define H_DIM 1024
#define N_EXP 8
#define I_DIM 128
#define V_DIM 32000
#define T_TOK 4096
#define EPSF 1.1920928955078125e-07f

extern __shared__ char dyn_smem[];

// ------------------- scratch (static device globals; no allocs) -------------------
__device__ float  g_x1[T_TOK * H_DIM];
__device__ float  g_moe[T_TOK * H_DIM];
__device__ int    g_cnt[N_EXP];
__device__ int    g_list[N_EXP * T_TOK];
__device__ float  g_wlist[N_EXP * T_TOK];
__device__ __half g_x1h[T_TOK * H_DIM];            // x1 in fp16 (for MoE gather)
__device__ __half g_gh[N_EXP * T_TOK * I_DIM];     // gate output fp16
__device__ __half g_egw_h[N_EXP * I_DIM * H_DIM];  // expert gate weights fp16
__device__ __half g_euw_h[N_EXP * H_DIM * I_DIM];  // expert up weights fp16
__device__ __half g_Ap[T_TOK * H_DIM];             // x2 in fp16, K=1024
__device__ __half g_Wh[(size_t)V_DIM * H_DIM];     // head_w in fp16, 64MB
// LoRA weights fp16: [0]=qA [1]=kA [2]=vA [3]=qB^T [4]=kB^T [5]=vB^T [6]=oA [7]=oB^T
__device__ __half g_loraw[8 * 8192];

// ------------------- LoRA weights -> fp16 (+ g_cnt zero) -------------------
__global__ __launch_bounds__(256) void loraconv_kernel(
    const float* __restrict__ qA, const float* __restrict__ qB,
    const float* __restrict__ kA, const float* __restrict__ kB,
    const float* __restrict__ vA, const float* __restrict__ vB,
    const float* __restrict__ oA, const float* __restrict__ oB)
{
    int idx = blockIdx.x * 256 + threadIdx.x;       // 32 blocks -> 8192 indices
    if (blockIdx.x == 0 && threadIdx.x < N_EXP) g_cnt[threadIdx.x] = 0;
    g_loraw[0 * 8192 + idx] = __float2half(qA[idx]);
    g_loraw[1 * 8192 + idx] = __float2half(kA[idx]);
    g_loraw[2 * 8192 + idx] = __float2half(vA[idx]);
    g_loraw[6 * 8192 + idx] = __float2half(oA[idx]);
    int h = idx & 1023, j = idx >> 10;
    g_loraw[3 * 8192 + j * 1024 + h] = __float2half(qB[h * 8 + j]);
    g_loraw[4 * 8192 + j * 1024 + h] = __float2half(kB[h * 8 + j]);
    g_loraw[5 * 8192 + j * 1024 + h] = __float2half(vB[h * 8 + j]);
    g_loraw[7 * 8192 + j * 1024 + h] = __float2half(oB[h * 8 + j]);
}

// ------------------- fused LoRA chain + RMSNorm1 (+ g_moe zero): 8 tok/CTA --------
#define LORA_W_BYTES (8 * 8192 * 2)
#define LORA_SMEM (LORA_W_BYTES + 2 * H_DIM * 4)

__global__ __launch_bounds__(256) void lora_rms1_kernel(
    const float* __restrict__ x, const float* __restrict__ n1w)
{
    __half* ws = (__half*)dyn_smem;
    float* sx = (float*)(dyn_smem + LORA_W_BYTES);
    float* ss = sx + H_DIM;
    __shared__ float red[8 * 24];
    __shared__ float us[24];
    __shared__ float ts[8];
    __shared__ float sinv;

    int tid = threadIdx.x, lane = tid & 31, wid = tid >> 5;

#pragma unroll
    for (int i = 0; i < 32; i++) {
        int q = tid + i * 256;
        ((uint4*)ws)[q] = ((const uint4*)g_loraw)[q];
    }
    __syncthreads();

    const __half* qA_s = ws;
    const __half* kA_s = ws + 8192;
    const __half* vA_s = ws + 2 * 8192;
    const __half* qBt  = ws + 3 * 8192;
    const __half* kBt  = ws + 4 * 8192;
    const __half* vBt  = ws + 5 * 8192;
    const __half* oA_s = ws + 6 * 8192;
    const __half* oBt  = ws + 7 * 8192;

    for (int tt = 0; tt < 8; tt++) {
        int t = blockIdx.x * 8 + tt;
        const float* xr = x + (size_t)t * H_DIM;
#pragma unroll
        for (int c = 0; c < 4; c++) sx[c * 256 + tid] = xr[c * 256 + tid];
        __syncthreads();

        float pu[24];
#pragma unroll
        for (int j = 0; j < 24; j++) pu[j] = 0.f;
#pragma unroll
        for (int c = 0; c < 4; c++) {
            int h = c * 256 + tid; float xv = sx[h];
#pragma unroll
            for (int j = 0; j < 8; j++) {
                pu[j]      += xv * __half2float(qA_s[j * 1024 + h]);
                pu[8 + j]  += xv * __half2float(kA_s[j * 1024 + h]);
                pu[16 + j] += xv * __half2float(vA_s[j * 1024 + h]);
            }
        }
#pragma unroll
        for (int j = 0; j < 24; j++)
#pragma unroll
            for (int o = 16; o; o >>= 1) pu[j] += __shfl_xor_sync(0xffffffffu, pu[j], o);
        if (lane == 0)
            for (int j = 0; j < 24; j++) red[wid * 24 + j] = pu[j];
        __syncthreads();
        if (tid < 24) {
            float s = 0.f;
            for (int w = 0; w < 8; w++) s += red[w * 24 + tid];
            us[tid] = s;
        }
        __syncthreads();

#pragma unroll
        for (int c = 0; c < 4; c++) {
            int h = c * 256 + tid; float s = 0.f;
#pragma unroll
            for (int j = 0; j < 8; j++)
                s += us[j]      * __half2float(qBt[j * 1024 + h])
                   + us[8 + j]  * __half2float(kBt[j * 1024 + h])
                   + us[16 + j] * __half2float(vBt[j * 1024 + h]);
            ss[h] = 2.f * s;
        }
        __syncthreads();

        float pt[8];
#pragma unroll
        for (int j = 0; j < 8; j++) pt[j] = 0.f;
#pragma unroll
        for (int c = 0; c < 4; c++) {
            int h = c * 256 + tid; float sv = ss[h];
#pragma unroll
            for (int j = 0; j < 8; j++) pt[j] += sv * __half2float(oA_s[j * 1024 + h]);
        }
#pragma unroll
        for (int j = 0; j < 8; j++)
#pragma unroll
            for (int o = 16; o; o >>= 1) pt[j] += __shfl_xor_sync(0xffffffffu, pt[j], o);
        if (lane == 0)
            for (int j = 0; j < 8; j++) red[wid * 8 + j] = pt[j];
        __syncthreads();
        if (tid < 8) {
            float s = 0.f;
            for (int w = 0; w < 8; w++) s += red[w * 8 + tid];
            ts[tid] = s;
        }
        __syncthreads();

        float ssq = 0.f;
#pragma unroll
        for (int c = 0; c < 4; c++) {
            int h = c * 256 + tid; float a = 0.f;
#pragma unroll
            for (int j = 0; j < 8; j++) a += ts[j] * __half2float(oBt[j * 1024 + h]);
            float pre = sx[h] + 2.f * a;
            ssq += pre * pre;
            ss[h] = pre;
        }
#pragma unroll
        for (int o = 16; o; o >>= 1) ssq += __shfl_xor_sync(0xffffffffu, ssq, o);
        if (lane == 0) red[wid] = ssq;
        __syncthreads();
        if (tid == 0) {
            float s = 0.f;
            for (int w = 0; w < 8; w++) s += red[w];
            sinv = rsqrtf(s * (1.f / H_DIM) + EPSF);
        }
        __syncthreads();
        float inv = sinv;
#pragma unroll
        for (int c = 0; c < 4; c++) {
            int h = c * 256 + tid;
            float v = ss[h] * inv * n1w[h];
            g_x1[(size_t)t * H_DIM + h] = v;
            g_x1h[(size_t)t * H_DIM + h] = __float2half(v);
            g_moe[(size_t)t * H_DIM + h] = 0.f;
        }
        __syncthreads();
    }
}

// ------------------- router -------------------
__global__ __launch_bounds__(256) void router_kernel(const float* __restrict__ rw)
{
    int t = blockIdx.x * 8 + (threadIdx.x >> 5);
    int lane = threadIdx.x & 31;
    const float* xr = g_x1 + (size_t)t * H_DIM;
    float acc[8];
#pragma unroll
    for (int e = 0; e < 8; e++) acc[e] = 0.f;
    for (int h = lane; h < H_DIM; h += 32) {
        float xv = xr[h];
#pragma unroll
        for (int e = 0; e < 8; e++) acc[e] += xv * rw[e * H_DIM + h];
    }
#pragma unroll
    for (int e = 0; e < 8; e++)
#pragma unroll
        for (int o = 16; o; o >>= 1) acc[e] += __shfl_xor_sync(0xffffffffu, acc[e], o);
    if (lane == 0) {
        int i1 = 0; float v1 = acc[0];
        for (int e = 1; e < 8; e++) if (acc[e] > v1) { v1 = acc[e]; i1 = e; }
        int i2 = -1; float v2 = -3.4e38f;
        for (int e = 0; e < 8; e++) if (e != i1 && acc[e] > v2) { v2 = acc[e]; i2 = e; }
        float ex = expf(v2 - v1);
        float w1 = 1.f / (1.f + ex);
        float w2 = ex * w1;
        int p1 = atomicAdd(&g_cnt[i1], 1);
        g_list[i1 * T_TOK + p1] = t; g_wlist[i1 * T_TOK + p1] = w1;
        int p2 = atomicAdd(&g_cnt[i2], 1);
        g_list[i2 * T_TOK + p2] = t; g_wlist[i2 * T_TOK + p2] = w2;
    }
}

// ------------------- expert weights -> fp16 -------------------
__global__ __launch_bounds__(256) void moeconv_kernel(
    const float* __restrict__ egw, const float* __restrict__ euw)
{
    size_t i = ((size_t)blockIdx.x * 256 + threadIdx.x) * 4;
    {
        float4 v = *(const float4*)(egw + i);
        __half2 h0 = __floats2half2_rn(v.x, v.y);
        __half2 h1 = __floats2half2_rn(v.z, v.w);
        uint2 pk; pk.x = *(uint32_t*)&h0; pk.y = *(uint32_t*)&h1;
        *(uint2*)(g_egw_h + i) = pk;
    }
    {
        float4 v = *(const float4*)(euw + i);
        __half2 h0 = __floats2half2_rn(v.x, v.y);
        __half2 h1 = __floats2half2_rn(v.z, v.w);
        uint2 pk; pk.x = *(uint32_t*)&h0; pk.y = *(uint32_t*)&h1;
        *(uint2*)(g_euw_h + i) = pk;
    }
}

// ------------------- gate MMA: g = silu(x1h_gathered @ egw_h[e]^T + egb[e]) ------
#define MOE_LDA 40
#define MOE_X_BYTES (32 * MOE_LDA * 2)
#define MOE_W_BYTES (128 * MOE_LDA * 2)
#define MOE_STAGE (MOE_X_BYTES + MOE_W_BYTES)

__global__ __launch_bounds__(128) void gate_mma_kernel(const float* __restrict__ egb)
{
    int e = blockIdx.y;
    int cnt = g_cnt[e];
    int t0 = blockIdx.x * 32;
    if (t0 >= cnt) return;

    __shared__ char smem[3 * MOE_STAGE];
    __shared__ int stok[32];
    int tid = threadIdx.x, lane = tid & 31, wid = tid >> 5;
    if (tid < 32) {
        int p = t0 + tid;
        stok[tid] = (p < cnt) ? g_list[e * T_TOK + p] : -1;
    }
    __syncthreads();

    int wm = (wid & 1) * 16;
    int wn = (wid >> 1) * 64;
    float acc[8][4];
#pragma unroll
    for (int a = 0; a < 8; a++)
#pragma unroll
        for (int b = 0; b < 4; b++) acc[a][b] = 0.f;

    const __half* wsrc = g_egw_h + (size_t)e * I_DIM * H_DIM;

    auto load_tile = [&](int s, int kb) {
        int ka = kb * 32;
        char* sX = smem + s * MOE_STAGE;
        char* sW = sX + MOE_X_BYTES;
        {
            int r = tid >> 2, c = tid & 3;
            int tok = stok[r];
            uint32_t dx = (uint32_t)__cvta_generic_to_shared(sX + r * 80 + c * 16);
            if (tok >= 0) {
                const __half* gx = g_x1h + (size_t)tok * H_DIM + ka + c * 8;
                asm volatile("cp.async.cg.shared.global [%0], [%1], 16;\n" :: "r"(dx), "l"(gx));
            } else {
                asm volatile("st.shared.v4.b32 [%0], {%1,%1,%1,%1};\n" :: "r"(dx), "r"(0u));
            }
        }
#pragma unroll
        for (int i = 0; i < 4; i++) {
            int q = tid + i * 128;
            int r = q >> 2, c = q & 3;
            const __half* gw = wsrc + (size_t)r * H_DIM + ka + c * 8;
            uint32_t dw = (uint32_t)__cvta_generic_to_shared(sW + r * 80 + c * 16);
            asm volatile("cp.async.cg.shared.global [%0], [%1], 16;\n" :: "r"(dw), "l"(gw));
        }
    };

    load_tile(0, 0);
    asm volatile("cp.async.commit_group;\n");
    load_tile(1, 1);
    asm volatile("cp.async.commit_group;\n");

    for (int kb = 0; kb < 32; kb++) {
        int s = kb % 3;
        asm volatile("cp.async.wait_group 1;\n");
        __syncthreads();
        if (kb + 2 < 32) load_tile((kb + 2) % 3, kb + 2);
        asm volatile("cp.async.commit_group;\n");

        uint32_t x_base = (uint32_t)__cvta_generic_to_shared(smem + s * MOE_STAGE);
        uint32_t w_base = x_base + MOE_X_BYTES;
#pragma unroll
        for (int kf = 0; kf < 2; kf++) {
            uint32_t ar[4], br[8][2];
            {
                int m = wm + (lane & 15);
                int k = kf * 16 + (lane >> 4) * 8;
                uint32_t addr = x_base + (uint32_t)(m * MOE_LDA + k) * 2;
                asm volatile("ldmatrix.sync.aligned.m8n8.x4.shared.b16 {%0,%1,%2,%3}, [%4];\n"
                    : "=r"(ar[0]), "=r"(ar[1]), "=r"(ar[2]), "=r"(ar[3]) : "r"(addr));
            }
#pragma unroll
            for (int np = 0; np < 4; np++) {
                int n = wn + np * 16 + (lane >> 4) * 8 + (lane & 7);
                int k = kf * 16 + ((lane >> 3) & 1) * 8;
                uint32_t addr = w_base + (uint32_t)(n * MOE_LDA + k) * 2;
                uint32_t r0, r1, r2, r3;
                asm volatile("ldmatrix.sync.aligned.m8n8.x4.shared.b16 {%0,%1,%2,%3}, [%4];\n"
                    : "=r"(r0), "=r"(r1), "=r"(r2), "=r"(r3) : "r"(addr));
                br[np * 2][0] = r0; br[np * 2][1] = r1;
                br[np * 2 + 1][0] = r2; br[np * 2 + 1][1] = r3;
            }
#pragma unroll
            for (int nf = 0; nf < 8; nf++) {
                float* c = acc[nf];
                asm volatile(
                    "mma.sync.aligned.m16n8k16.row.col.f32.f16.f16.f32 "
                    "{%0,%1,%2,%3}, {%4,%5,%6,%7}, {%8,%9}, {%0,%1,%2,%3};\n"
                    : "+f"(c[0]), "+f"(c[1]), "+f"(c[2]), "+f"(c[3])
                    : "r"(ar[0]), "r"(ar[1]), "r"(ar[2]), "r"(ar[3]),
                      "r"(br[nf][0]), "r"(br[nf][1]));
            }
        }
        __syncthreads();
    }

    int g = lane >> 2, tq = lane & 3;
    int row0 = wm + g, row1 = wm + g + 8;
#pragma unroll
    for (int nf = 0; nf < 8; nf++) {
        int col = wn + nf * 8 + tq * 2;
        float b0 = egb[e * I_DIM + col], b1 = egb[e * I_DIM + col + 1];
        if (t0 + row0 < cnt) {
            float v0 = acc[nf][0] + b0, v1 = acc[nf][1] + b1;
            v0 = v0 / (1.f + expf(-v0));
            v1 = v1 / (1.f + expf(-v1));
            *(__half2*)&g_gh[(size_t)(e * T_TOK + t0 + row0) * I_DIM + col] =
                __floats2half2_rn(v0, v1);
        }
        if (t0 + row1 < cnt) {
            float v0 = acc[nf][2] + b0, v1 = acc[nf][3] + b1;
            v0 = v0 / (1.f + expf(-v0));
            v1 = v1 / (1.f + expf(-v1));
            *(__half2*)&g_gh[(size_t)(e * T_TOK + t0 + row1) * I_DIM + col] =
                __floats2half2_rn(v0, v1);
        }
    }
}

// ------------------- up MMA: y = g @ euw_h[e]^T + eub[e], weighted scatter-add ----
__global__ __launch_bounds__(128) void up_mma_kernel(const float* __restrict__ eub)
{
    int e = blockIdx.z;
    int cnt = g_cnt[e];
    int t0 = blockIdx.x * 32;
    if (t0 >= cnt) return;
    int h0 = blockIdx.y * 128;

    __shared__ char smem[3 * MOE_STAGE];
    __shared__ int stok[32];
    __shared__ float swt[32];
    int tid = threadIdx.x, lane = tid & 31, wid = tid >> 5;
    if (tid < 32) {
        int p = t0 + tid;
        if (p < cnt) { stok[tid] = g_list[e * T_TOK + p]; swt[tid] = g_wlist[e * T_TOK + p]; }
        else { stok[tid] = -1; swt[tid] = 0.f; }
    }
    __syncthreads();

    int wm = (wid & 1) * 16;
    int wn = (wid >> 1) * 64;
    float acc[8][4];
#pragma unroll
    for (int a = 0; a < 8; a++)
#pragma unroll
        for (int b = 0; b < 4; b++) acc[a][b] = 0.f;

    const __half* gsrc = g_gh + (size_t)e * T_TOK * I_DIM;
    const __half* wsrc = g_euw_h + (size_t)e * H_DIM * I_DIM;

    auto load_tile = [&](int s, int kb) {
        int ka = kb * 32;
        char* sX = smem + s * MOE_STAGE;
        char* sW = sX + MOE_X_BYTES;
        {
            int r = tid >> 2, c = tid & 3;
            const __half* gx = gsrc + (size_t)(t0 + r) * I_DIM + ka + c * 8;
            uint32_t dx = (uint32_t)__cvta_generic_to_shared(sX + r * 80 + c * 16);
            asm volatile("cp.async.cg.shared.global [%0], [%1], 16;\n" :: "r"(dx), "l"(gx));
        }
#pragma unroll
        for (int i = 0; i < 4; i++) {
            int q = tid + i * 128;
            int r = q >> 2, c = q & 3;
            const __half* gw = wsrc + (size_t)(h0 + r) * I_DIM + ka + c * 8;
            uint32_t dw = (uint32_t)__cvta_generic_to_shared(sW + r * 80 + c * 16);
            asm volatile("cp.async.cg.shared.global [%0], [%1], 16;\n" :: "r"(dw), "l"(gw));
        }
    };

    load_tile(0, 0);
    asm volatile("cp.async.commit_group;\n");
    load_tile(1, 1);
    asm volatile("cp.async.commit_group;\n");

    for (int kb = 0; kb < 4; kb++) {
        int s = kb % 3;
        asm volatile("cp.async.wait_group 1;\n");
        __syncthreads();
        if (kb + 2 < 4) load_tile((kb + 2) % 3, kb + 2);
        asm volatile("cp.async.commit_group;\n");

        uint32_t x_base = (uint32_t)__cvta_generic_to_shared(smem + s * MOE_STAGE);
        uint32_t w_base = x_base + MOE_X_BYTES;
#pragma unroll
        for (int kf = 0; kf < 2; kf++) {
            uint32_t ar[4], br[8][2];
            {
                int m = wm + (lane & 15);
                int k = kf * 16 + (lane >> 4) * 8;
                uint32_t addr = x_base + (uint32_t)(m * MOE_LDA + k) * 2;
                asm volatile("ldmatrix.sync.aligned.m8n8.x4.shared.b16 {%0,%1,%2,%3}, [%4];\n"
                    : "=r"(ar[0]), "=r"(ar[1]), "=r"(ar[2]), "=r"(ar[3]) : "r"(addr));
            }
#pragma unroll
            for (int np = 0; np < 4; np++) {
                int n = wn + np * 16 + (lane >> 4) * 8 + (lane & 7);
                int k = kf * 16 + ((lane >> 3) & 1) * 8;
                uint32_t addr = w_base + (uint32_t)(n * MOE_LDA + k) * 2;
                uint32_t r0, r1, r2, r3;
                asm volatile("ldmatrix.sync.aligned.m8n8.x4.shared.b16 {%0,%1,%2,%3}, [%4];\n"
                    : "=r"(r0), "=r"(r1), "=r"(r2), "=r"(r3) : "r"(addr));
                br[np * 2][0] = r0; br[np * 2][1] = r1;
                br[np * 2 + 1][0] = r2; br[np * 2 + 1][1] = r3;
            }
#pragma unroll
            for (int nf = 0; nf < 8; nf++) {
                float* c = acc[nf];
                asm volatile(
                    "mma.sync.aligned.m16n8k16.row.col.f32.f16.f16.f32 "
                    "{%0,%1,%2,%3}, {%4,%5,%6,%7}, {%8,%9}, {%0,%1,%2,%3};\n"
                    : "+f"(c[0]), "+f"(c[1]), "+f"(c[2]), "+f"(c[3])
                    : "r"(ar[0]), "r"(ar[1]), "r"(ar[2]), "r"(ar[3]),
                      "r"(br[nf][0]), "r"(br[nf][1]));
            }
        }
        __syncthreads();
    }

    int g = lane >> 2, tq = lane & 3;
    int row0 = wm + g, row1 = wm + g + 8;
    int tok0 = stok[row0], tok1 = stok[row1];
    float w0 = swt[row0], w1 = swt[row1];
#pragma unroll
    for (int nf = 0; nf < 8; nf++) {
        int col = h0 + wn + nf * 8 + tq * 2;
        float b0 = eub[e * H_DIM + col], b1 = eub[e * H_DIM + col + 1];
        if (tok0 >= 0) {
            atomicAdd(&g_moe[(size_t)tok0 * H_DIM + col],     w0 * (acc[nf][0] + b0));
            atomicAdd(&g_moe[(size_t)tok0 * H_DIM + col + 1], w0 * (acc[nf][1] + b1));
        }
        if (tok1 >= 0) {
            atomicAdd(&g_moe[(size_t)tok1 * H_DIM + col],     w1 * (acc[nf][2] + b0));
            atomicAdd(&g_moe[(size_t)tok1 * H_DIM + col + 1], w1 * (acc[nf][3] + b1));
        }
    }
}

// ------------------- RMSNorm2 + fp16 A' build (K=1024) -------------------
__global__ __launch_bounds__(256) void rms2_split_kernel(const float* __restrict__ n2w)
{
    int t = blockIdx.x;
    int tid = threadIdx.x, lane = tid & 31, wid = tid >> 5;
    __shared__ float red[8];
    __shared__ float sinv;
    float pre[4]; float ssq = 0.f;
#pragma unroll
    for (int c = 0; c < 4; c++) {
        int h = c * 256 + tid;
        float p = g_x1[(size_t)t * H_DIM + h] + g_moe[(size_t)t * H_DIM + h];
        pre[c] = p; ssq += p * p;
    }
#pragma unroll
    for (int o = 16; o; o >>= 1) ssq += __shfl_xor_sync(0xffffffffu, ssq, o);
    if (lane == 0) red[wid] = ssq;
    __syncthreads();
    if (tid == 0) {
        float s = 0.f;
        for (int w = 0; w < 8; w++) s += red[w];
        sinv = rsqrtf(s * (1.f / H_DIM) + EPSF);
    }
    __syncthreads();
    float inv = sinv;
#pragma unroll
    for (int c = 0; c < 4; c++) {
        int h = c * 256 + tid;
        float v = pre[c] * inv * n2w[h];
        g_Ap[(size_t)t * H_DIM + h] = __float2half(v);
    }
}

// ------------------- head_w -> fp16 -------------------
__global__ __launch_bounds__(256) void wconv_kernel(const float* __restrict__ w)
{
    size_t i = ((size_t)blockIdx.x * 256 + threadIdx.x) * 8;
    float4 v0 = *(const float4*)(w + i);
    float4 v1 = *(const float4*)(w + i + 4);
    __half2 h0 = __floats2half2_rn(v0.x, v0.y);
    __half2 h1 = __floats2half2_rn(v0.z, v0.w);
    __half2 h2 = __floats2half2_rn(v1.x, v1.y);
    __half2 h3 = __floats2half2_rn(v1.z, v1.w);
    uint4 pk;
    pk.x = *(uint32_t*)&h0; pk.y = *(uint32_t*)&h1;
    pk.z = *(uint32_t*)&h2; pk.w = *(uint32_t*)&h3;
    *(uint4*)(g_Wh + i) = pk;
}

// ------------------- head GEMM: out[4096,32000] = Ap[4096,1024] @ Wh[32000,1024]^T
// 128x256 CTA tile, BK=128 (256B smem rows, 8 pad halves), 2-stage double buffer.
#define LDA_S 136                      // 128 halves + 8 pad = 272B rows; 17m mod 8 bijective
#define HG_A_BYTES (128 * LDA_S * 2)   // 34816
#define HG_B_BYTES (256 * LDA_S * 2)   // 69632
#define HG_STAGE_BYTES (HG_A_BYTES + HG_B_BYTES)   // 104448
#define HG_STAGES 2
#define HG_KB 8
#define HG_SMEM (HG_STAGES * HG_STAGE_BYTES)       // 208896

__global__ __launch_bounds__(256, 1) void head_gemm_kernel(float* __restrict__ out)
{
    char* smem = dyn_smem;

    int bid = blockIdx.x;
    const int GROUP = 16;
    int group = bid / (GROUP * 125);
    int rem = bid % (GROUP * 125);
    int bm = group * GROUP + (rem % GROUP);
    int bn = rem / GROUP;
    int m0 = bm * 128, n0 = bn * 256;

    int tid = threadIdx.x;
    int lane = tid & 31, wid = tid >> 5;
    int wm = (wid & 1) * 64;
    int wn = (wid >> 1) * 64;

    float acc[4][8][4];
#pragma unroll
    for (int a = 0; a < 4; a++)
#pragma unroll
        for (int b = 0; b < 8; b++)
#pragma unroll
            for (int c = 0; c < 4; c++) acc[a][b][c] = 0.f;

    auto load_tile = [&](int s, int kb) {
        int ka = kb * 128;
        char* sA = smem + s * HG_STAGE_BYTES;
        char* sB = sA + HG_A_BYTES;
#pragma unroll
        for (int i = 0; i < 8; i++) {
            int q = tid + i * 256;
            int r = q >> 4, c = q & 15;
            const __half* ga = g_Ap + (size_t)(m0 + r) * H_DIM + ka + c * 8;
            uint32_t da = (uint32_t)__cvta_generic_to_shared(sA + r * 272 + c * 16);
            asm volatile("cp.async.cg.shared.global [%0], [%1], 16;\n" :: "r"(da), "l"(ga));
        }
#pragma unroll
        for (int i = 0; i < 16; i++) {
            int q = tid + i * 256;
            int r = q >> 4, c = q & 15;
            const __half* gb = g_Wh + (size_t)(n0 + r) * H_DIM + ka + c * 8;
            uint32_t db = (uint32_t)__cvta_generic_to_shared(sB + r * 272 + c * 16);
            asm volatile("cp.async.cg.shared.global [%0], [%1], 16;\n" :: "r"(db), "l"(gb));
        }
    };

    load_tile(0, 0);
    asm volatile("cp.async.commit_group;\n");
    load_tile(1, 1);
    asm volatile("cp.async.commit_group;\n");

    for (int kb = 0; kb < HG_KB; kb++) {
        int s = kb & 1;
        asm volatile("cp.async.wait_group 1;\n");
        __syncthreads();

        uint32_t a_base = (uint32_t)__cvta_generic_to_shared(smem + s * HG_STAGE_BYTES);
        uint32_t b_base = a_base + HG_A_BYTES;
#pragma unroll
        for (int kf = 0; kf < 8; kf++) {
            uint32_t ar[4][4], br[8][2];
#pragma unroll
            for (int mf = 0; mf < 4; mf++) {
                int m = wm + mf * 16 + (lane & 15);
                int k = kf * 16 + (lane >> 4) * 8;
                uint32_t addr = a_base + (uint32_t)(m * LDA_S + k) * 2;
                asm volatile("ldmatrix.sync.aligned.m8n8.x4.shared.b16 {%0,%1,%2,%3}, [%4];\n"
                    : "=r"(ar[mf][0]), "=r"(ar[mf][1]), "=r"(ar[mf][2]), "=r"(ar[mf][3])
                    : "r"(addr));
            }
#pragma unroll
            for (int np = 0; np < 4; np++) {
                int n = wn + np * 16 + (lane >> 4) * 8 + (lane & 7);
                int k = kf * 16 + ((lane >> 3) & 1) * 8;
                uint32_t addr = b_base + (uint32_t)(n * LDA_S + k) * 2;
                uint32_t r0, r1, r2, r3;
                asm volatile("ldmatrix.sync.aligned.m8n8.x4.shared.b16 {%0,%1,%2,%3}, [%4];\n"
                    : "=r"(r0), "=r"(r1), "=r"(r2), "=r"(r3) : "r"(addr));
                br[np * 2][0] = r0; br[np * 2][1] = r1;
                br[np * 2 + 1][0] = r2; br[np * 2 + 1][1] = r3;
            }
#pragma unroll
            for (int mf = 0; mf < 4; mf++)
#pragma unroll
                for (int nf = 0; nf < 8; nf++) {
                    float* c = acc[mf][nf];
                    asm volatile(
                        "mma.sync.aligned.m16n8k16.row.col.f32.f16.f16.f32 "
                        "{%0,%1,%2,%3}, {%4,%5,%6,%7}, {%8,%9}, {%0,%1,%2,%3};\n"
                        : "+f"(c[0]), "+f"(c[1]), "+f"(c[2]), "+f"(c[3])
                        : "r"(ar[mf][0]), "r"(ar[mf][1]), "r"(ar[mf][2]), "r"(ar[mf][3]),
                          "r"(br[nf][0]), "r"(br[nf][1]));
                }
        }

        // done reading stage s; refill it with kb+2 (overlaps compute of kb+1)
        __syncthreads();
        if (kb + 2 < HG_KB) {
            load_tile(s, kb + 2);
            asm volatile("cp.async.commit_group;\n");
        }
    }

    int g = lane >> 2, tq = lane & 3;
#pragma unroll
    for (int mf = 0; mf < 4; mf++) {
#pragma unroll
        for (int nf = 0; nf < 8; nf++) {
            int row = m0 + wm + mf * 16 + g;
            int col = n0 + wn + nf * 8 + tq * 2;
            *(float2*)&out[(size_t)row * V_DIM + col] =
                make_float2(acc[mf][nf][0], acc[mf][nf][1]);
            *(float2*)&out[(size_t)(row + 8) * V_DIM + col] =
                make_float2(acc[mf][nf][2], acc[mf][nf][3]);
        }
    }
}

// ------------------- launch -------------------
extern "C" void kernel_launch(void* const* d_in, const int* in_sizes, int n_in,
                              void* d_out, int out_size)
{
    const float* x    = (const float*)d_in[0];
    const float* qA   = (const float*)d_in[1];
    const float* qB   = (const float*)d_in[2];
    const float* kA   = (const float*)d_in[3];
    const float* kB   = (const float*)d_in[4];
    const float* vA   = (const float*)d_in[5];
    const float* vB   = (const float*)d_in[6];
    const float* oA   = (const float*)d_in[7];
    const float* oB   = (const float*)d_in[8];
    const float* n1w  = (const float*)d_in[9];
    const float* n2w  = (const float*)d_in[10];
    const float* rw   = (const float*)d_in[11];
    const float* egw  = (const float*)d_in[12];
    const float* egb  = (const float*)d_in[13];
    const float* euw  = (const float*)d_in[14];
    const float* eub  = (const float*)d_in[15];
    const float* hw   = (const float*)d_in[16];
    float* out = (float*)d_out;

    static bool attr_set = false;
    if (!attr_set) {
        cudaFuncSetAttribute(head_gemm_kernel,
                             cudaFuncAttributeMaxDynamicSharedMemorySize, HG_SMEM);
        cudaFuncSetAttribute(lora_rms1_kernel,
                             cudaFuncAttributeMaxDynamicSharedMemorySize, LORA_SMEM);
        attr_set = true;
    }

    loraconv_kernel<<<32, 256>>>(qA, qB, kA, kB, vA, vB, oA, oB);
    lora_rms1_kernel<<<512, 256, LORA_SMEM>>>(x, n1w);
    router_kernel<<<512, 256>>>(rw);
    moeconv_kernel<<<1024, 256>>>(egw, euw);
    gate_mma_kernel<<<dim3(128, 8), 128>>>(egb);
    up_mma_kernel<<<dim3(128, 8, 8), 128>>>(eub);
    rms2_split_kernel<<<4096, 256>>>(n2w);
    wconv_kernel<<<16000, 256>>>(hw);
    head_gemm_kernel<<<4000, 256, HG_SMEM>>>(out);
}

// round 17
// speedup vs baseline: 1.0133x; 1.0133x over previous
#include <cuda_runtime.h>
#include <cuda_bf16.h>
#include <cuda_fp16.h>
#include <cstdint>

#define H_DIM 1024
#define N_EXP 8
#define I_DIM 128
#define V_DIM 32000
#define T_TOK 4096
#define EPSF 1.1920928955078125e-07f

extern __shared__ char dyn_smem[];

// ------------------- scratch (static device globals; no allocs) -------------------
__device__ float  g_x1[T_TOK * H_DIM];
__device__ float  g_moe[T_TOK * H_DIM];
__device__ int    g_cnt[N_EXP];
__device__ int    g_list[N_EXP * T_TOK];
__device__ float  g_wlist[N_EXP * T_TOK];
__device__ __half g_x1h[T_TOK * H_DIM];            // x1 in fp16 (for MoE gather)
__device__ __half g_gh[N_EXP * T_TOK * I_DIM];     // gate output fp16
__device__ __half g_egw_h[N_EXP * I_DIM * H_DIM];  // expert gate weights fp16
__device__ __half g_euw_h[N_EXP * H_DIM * I_DIM];  // expert up weights fp16
__device__ __half g_Ap[T_TOK * H_DIM];             // x2 in fp16, K=1024
__device__ __half g_Wh[(size_t)V_DIM * H_DIM];     // head_w in fp16, 64MB
// LoRA weights fp16: [0]=qA [1]=kA [2]=vA [3]=qB^T [4]=kB^T [5]=vB^T [6]=oA [7]=oB^T
__device__ __half g_loraw[8 * 8192];

// ------------------- LoRA weights -> fp16 (+ g_cnt zero) -------------------
__global__ __launch_bounds__(256) void loraconv_kernel(
    const float* __restrict__ qA, const float* __restrict__ qB,
    const float* __restrict__ kA, const float* __restrict__ kB,
    const float* __restrict__ vA, const float* __restrict__ vB,
    const float* __restrict__ oA, const float* __restrict__ oB)
{
    int idx = blockIdx.x * 256 + threadIdx.x;       // 32 blocks -> 8192 indices
    if (blockIdx.x == 0 && threadIdx.x < N_EXP) g_cnt[threadIdx.x] = 0;
    g_loraw[0 * 8192 + idx] = __float2half(qA[idx]);
    g_loraw[1 * 8192 + idx] = __float2half(kA[idx]);
    g_loraw[2 * 8192 + idx] = __float2half(vA[idx]);
    g_loraw[6 * 8192 + idx] = __float2half(oA[idx]);
    int h = idx & 1023, j = idx >> 10;
    g_loraw[3 * 8192 + j * 1024 + h] = __float2half(qB[h * 8 + j]);
    g_loraw[4 * 8192 + j * 1024 + h] = __float2half(kB[h * 8 + j]);
    g_loraw[5 * 8192 + j * 1024 + h] = __float2half(vB[h * 8 + j]);
    g_loraw[7 * 8192 + j * 1024 + h] = __float2half(oB[h * 8 + j]);
}

// ------------------- fused LoRA chain + RMSNorm1 (+ g_moe zero): 8 tok/CTA --------
#define LORA_W_BYTES (8 * 8192 * 2)
#define LORA_SMEM (LORA_W_BYTES + 2 * H_DIM * 4)

__global__ __launch_bounds__(256) void lora_rms1_kernel(
    const float* __restrict__ x, const float* __restrict__ n1w)
{
    __half* ws = (__half*)dyn_smem;
    float* sx = (float*)(dyn_smem + LORA_W_BYTES);
    float* ss = sx + H_DIM;
    __shared__ float red[8 * 24];
    __shared__ float us[24];
    __shared__ float ts[8];
    __shared__ float sinv;

    int tid = threadIdx.x, lane = tid & 31, wid = tid >> 5;

#pragma unroll
    for (int i = 0; i < 32; i++) {
        int q = tid + i * 256;
        ((uint4*)ws)[q] = ((const uint4*)g_loraw)[q];
    }
    __syncthreads();

    const __half* qA_s = ws;
    const __half* kA_s = ws + 8192;
    const __half* vA_s = ws + 2 * 8192;
    const __half* qBt  = ws + 3 * 8192;
    const __half* kBt  = ws + 4 * 8192;
    const __half* vBt  = ws + 5 * 8192;
    const __half* oA_s = ws + 6 * 8192;
    const __half* oBt  = ws + 7 * 8192;

    for (int tt = 0; tt < 8; tt++) {
        int t = blockIdx.x * 8 + tt;
        const float* xr = x + (size_t)t * H_DIM;
#pragma unroll
        for (int c = 0; c < 4; c++) sx[c * 256 + tid] = xr[c * 256 + tid];
        __syncthreads();

        float pu[24];
#pragma unroll
        for (int j = 0; j < 24; j++) pu[j] = 0.f;
#pragma unroll
        for (int c = 0; c < 4; c++) {
            int h = c * 256 + tid; float xv = sx[h];
#pragma unroll
            for (int j = 0; j < 8; j++) {
                pu[j]      += xv * __half2float(qA_s[j * 1024 + h]);
                pu[8 + j]  += xv * __half2float(kA_s[j * 1024 + h]);
                pu[16 + j] += xv * __half2float(vA_s[j * 1024 + h]);
            }
        }
#pragma unroll
        for (int j = 0; j < 24; j++)
#pragma unroll
            for (int o = 16; o; o >>= 1) pu[j] += __shfl_xor_sync(0xffffffffu, pu[j], o);
        if (lane == 0)
            for (int j = 0; j < 24; j++) red[wid * 24 + j] = pu[j];
        __syncthreads();
        if (tid < 24) {
            float s = 0.f;
            for (int w = 0; w < 8; w++) s += red[w * 24 + tid];
            us[tid] = s;
        }
        __syncthreads();

#pragma unroll
        for (int c = 0; c < 4; c++) {
            int h = c * 256 + tid; float s = 0.f;
#pragma unroll
            for (int j = 0; j < 8; j++)
                s += us[j]      * __half2float(qBt[j * 1024 + h])
                   + us[8 + j]  * __half2float(kBt[j * 1024 + h])
                   + us[16 + j] * __half2float(vBt[j * 1024 + h]);
            ss[h] = 2.f * s;
        }
        __syncthreads();

        float pt[8];
#pragma unroll
        for (int j = 0; j < 8; j++) pt[j] = 0.f;
#pragma unroll
        for (int c = 0; c < 4; c++) {
            int h = c * 256 + tid; float sv = ss[h];
#pragma unroll
            for (int j = 0; j < 8; j++) pt[j] += sv * __half2float(oA_s[j * 1024 + h]);
        }
#pragma unroll
        for (int j = 0; j < 8; j++)
#pragma unroll
            for (int o = 16; o; o >>= 1) pt[j] += __shfl_xor_sync(0xffffffffu, pt[j], o);
        if (lane == 0)
            for (int j = 0; j < 8; j++) red[wid * 8 + j] = pt[j];
        __syncthreads();
        if (tid < 8) {
            float s = 0.f;
            for (int w = 0; w < 8; w++) s += red[w * 8 + tid];
            ts[tid] = s;
        }
        __syncthreads();

        float ssq = 0.f;
#pragma unroll
        for (int c = 0; c < 4; c++) {
            int h = c * 256 + tid; float a = 0.f;
#pragma unroll
            for (int j = 0; j < 8; j++) a += ts[j] * __half2float(oBt[j * 1024 + h]);
            float pre = sx[h] + 2.f * a;
            ssq += pre * pre;
            ss[h] = pre;
        }
#pragma unroll
        for (int o = 16; o; o >>= 1) ssq += __shfl_xor_sync(0xffffffffu, ssq, o);
        if (lane == 0) red[wid] = ssq;
        __syncthreads();
        if (tid == 0) {
            float s = 0.f;
            for (int w = 0; w < 8; w++) s += red[w];
            sinv = rsqrtf(s * (1.f / H_DIM) + EPSF);
        }
        __syncthreads();
        float inv = sinv;
#pragma unroll
        for (int c = 0; c < 4; c++) {
            int h = c * 256 + tid;
            float v = ss[h] * inv * n1w[h];
            g_x1[(size_t)t * H_DIM + h] = v;
            g_x1h[(size_t)t * H_DIM + h] = __float2half(v);
            g_moe[(size_t)t * H_DIM + h] = 0.f;
        }
        __syncthreads();
    }
}

// ------------------- router -------------------
__global__ __launch_bounds__(256) void router_kernel(const float* __restrict__ rw)
{
    int t = blockIdx.x * 8 + (threadIdx.x >> 5);
    int lane = threadIdx.x & 31;
    const float* xr = g_x1 + (size_t)t * H_DIM;
    float acc[8];
#pragma unroll
    for (int e = 0; e < 8; e++) acc[e] = 0.f;
    for (int h = lane; h < H_DIM; h += 32) {
        float xv = xr[h];
#pragma unroll
        for (int e = 0; e < 8; e++) acc[e] += xv * rw[e * H_DIM + h];
    }
#pragma unroll
    for (int e = 0; e < 8; e++)
#pragma unroll
        for (int o = 16; o; o >>= 1) acc[e] += __shfl_xor_sync(0xffffffffu, acc[e], o);
    if (lane == 0) {
        int i1 = 0; float v1 = acc[0];
        for (int e = 1; e < 8; e++) if (acc[e] > v1) { v1 = acc[e]; i1 = e; }
        int i2 = -1; float v2 = -3.4e38f;
        for (int e = 0; e < 8; e++) if (e != i1 && acc[e] > v2) { v2 = acc[e]; i2 = e; }
        float ex = expf(v2 - v1);
        float w1 = 1.f / (1.f + ex);
        float w2 = ex * w1;
        int p1 = atomicAdd(&g_cnt[i1], 1);
        g_list[i1 * T_TOK + p1] = t; g_wlist[i1 * T_TOK + p1] = w1;
        int p2 = atomicAdd(&g_cnt[i2], 1);
        g_list[i2 * T_TOK + p2] = t; g_wlist[i2 * T_TOK + p2] = w2;
    }
}

// ------------------- expert weights -> fp16 -------------------
__global__ __launch_bounds__(256) void moeconv_kernel(
    const float* __restrict__ egw, const float* __restrict__ euw)
{
    size_t i = ((size_t)blockIdx.x * 256 + threadIdx.x) * 4;
    {
        float4 v = *(const float4*)(egw + i);
        __half2 h0 = __floats2half2_rn(v.x, v.y);
        __half2 h1 = __floats2half2_rn(v.z, v.w);
        uint2 pk; pk.x = *(uint32_t*)&h0; pk.y = *(uint32_t*)&h1;
        *(uint2*)(g_egw_h + i) = pk;
    }
    {
        float4 v = *(const float4*)(euw + i);
        __half2 h0 = __floats2half2_rn(v.x, v.y);
        __half2 h1 = __floats2half2_rn(v.z, v.w);
        uint2 pk; pk.x = *(uint32_t*)&h0; pk.y = *(uint32_t*)&h1;
        *(uint2*)(g_euw_h + i) = pk;
    }
}

// ------------------- gate MMA: g = silu(x1h_gathered @ egw_h[e]^T + egb[e]) ------
#define MOE_LDA 40
#define MOE_X_BYTES (32 * MOE_LDA * 2)
#define MOE_W_BYTES (128 * MOE_LDA * 2)
#define MOE_STAGE (MOE_X_BYTES + MOE_W_BYTES)

__global__ __launch_bounds__(128) void gate_mma_kernel(const float* __restrict__ egb)
{
    int e = blockIdx.y;
    int cnt = g_cnt[e];
    int t0 = blockIdx.x * 32;
    if (t0 >= cnt) return;

    __shared__ char smem[3 * MOE_STAGE];
    __shared__ int stok[32];
    int tid = threadIdx.x, lane = tid & 31, wid = tid >> 5;
    if (tid < 32) {
        int p = t0 + tid;
        stok[tid] = (p < cnt) ? g_list[e * T_TOK + p] : -1;
    }
    __syncthreads();

    int wm = (wid & 1) * 16;
    int wn = (wid >> 1) * 64;
    float acc[8][4];
#pragma unroll
    for (int a = 0; a < 8; a++)
#pragma unroll
        for (int b = 0; b < 4; b++) acc[a][b] = 0.f;

    const __half* wsrc = g_egw_h + (size_t)e * I_DIM * H_DIM;

    auto load_tile = [&](int s, int kb) {
        int ka = kb * 32;
        char* sX = smem + s * MOE_STAGE;
        char* sW = sX + MOE_X_BYTES;
        {
            int r = tid >> 2, c = tid & 3;
            int tok = stok[r];
            uint32_t dx = (uint32_t)__cvta_generic_to_shared(sX + r * 80 + c * 16);
            if (tok >= 0) {
                const __half* gx = g_x1h + (size_t)tok * H_DIM + ka + c * 8;
                asm volatile("cp.async.cg.shared.global [%0], [%1], 16;\n" :: "r"(dx), "l"(gx));
            } else {
                asm volatile("st.shared.v4.b32 [%0], {%1,%1,%1,%1};\n" :: "r"(dx), "r"(0u));
            }
        }
#pragma unroll
        for (int i = 0; i < 4; i++) {
            int q = tid + i * 128;
            int r = q >> 2, c = q & 3;
            const __half* gw = wsrc + (size_t)r * H_DIM + ka + c * 8;
            uint32_t dw = (uint32_t)__cvta_generic_to_shared(sW + r * 80 + c * 16);
            asm volatile("cp.async.cg.shared.global [%0], [%1], 16;\n" :: "r"(dw), "l"(gw));
        }
    };

    load_tile(0, 0);
    asm volatile("cp.async.commit_group;\n");
    load_tile(1, 1);
    asm volatile("cp.async.commit_group;\n");

    for (int kb = 0; kb < 32; kb++) {
        int s = kb % 3;
        asm volatile("cp.async.wait_group 1;\n");
        __syncthreads();
        if (kb + 2 < 32) load_tile((kb + 2) % 3, kb + 2);
        asm volatile("cp.async.commit_group;\n");

        uint32_t x_base = (uint32_t)__cvta_generic_to_shared(smem + s * MOE_STAGE);
        uint32_t w_base = x_base + MOE_X_BYTES;
#pragma unroll
        for (int kf = 0; kf < 2; kf++) {
            uint32_t ar[4], br[8][2];
            {
                int m = wm + (lane & 15);
                int k = kf * 16 + (lane >> 4) * 8;
                uint32_t addr = x_base + (uint32_t)(m * MOE_LDA + k) * 2;
                asm volatile("ldmatrix.sync.aligned.m8n8.x4.shared.b16 {%0,%1,%2,%3}, [%4];\n"
                    : "=r"(ar[0]), "=r"(ar[1]), "=r"(ar[2]), "=r"(ar[3]) : "r"(addr));
            }
#pragma unroll
            for (int np = 0; np < 4; np++) {
                int n = wn + np * 16 + (lane >> 4) * 8 + (lane & 7);
                int k = kf * 16 + ((lane >> 3) & 1) * 8;
                uint32_t addr = w_base + (uint32_t)(n * MOE_LDA + k) * 2;
                uint32_t r0, r1, r2, r3;
                asm volatile("ldmatrix.sync.aligned.m8n8.x4.shared.b16 {%0,%1,%2,%3}, [%4];\n"
                    : "=r"(r0), "=r"(r1), "=r"(r2), "=r"(r3) : "r"(addr));
                br[np * 2][0] = r0; br[np * 2][1] = r1;
                br[np * 2 + 1][0] = r2; br[np * 2 + 1][1] = r3;
            }
#pragma unroll
            for (int nf = 0; nf < 8; nf++) {
                float* c = acc[nf];
                asm volatile(
                    "mma.sync.aligned.m16n8k16.row.col.f32.f16.f16.f32 "
                    "{%0,%1,%2,%3}, {%4,%5,%6,%7}, {%8,%9}, {%0,%1,%2,%3};\n"
                    : "+f"(c[0]), "+f"(c[1]), "+f"(c[2]), "+f"(c[3])
                    : "r"(ar[0]), "r"(ar[1]), "r"(ar[2]), "r"(ar[3]),
                      "r"(br[nf][0]), "r"(br[nf][1]));
            }
        }
        __syncthreads();
    }

    int g = lane >> 2, tq = lane & 3;
    int row0 = wm + g, row1 = wm + g + 8;
#pragma unroll
    for (int nf = 0; nf < 8; nf++) {
        int col = wn + nf * 8 + tq * 2;
        float b0 = egb[e * I_DIM + col], b1 = egb[e * I_DIM + col + 1];
        if (t0 + row0 < cnt) {
            float v0 = acc[nf][0] + b0, v1 = acc[nf][1] + b1;
            v0 = v0 / (1.f + expf(-v0));
            v1 = v1 / (1.f + expf(-v1));
            *(__half2*)&g_gh[(size_t)(e * T_TOK + t0 + row0) * I_DIM + col] =
                __floats2half2_rn(v0, v1);
        }
        if (t0 + row1 < cnt) {
            float v0 = acc[nf][2] + b0, v1 = acc[nf][3] + b1;
            v0 = v0 / (1.f + expf(-v0));
            v1 = v1 / (1.f + expf(-v1));
            *(__half2*)&g_gh[(size_t)(e * T_TOK + t0 + row1) * I_DIM + col] =
                __floats2half2_rn(v0, v1);
        }
    }
}

// ------------------- up MMA: y = g @ euw_h[e]^T + eub[e], weighted scatter-add ----
__global__ __launch_bounds__(128) void up_mma_kernel(const float* __restrict__ eub)
{
    int e = blockIdx.z;
    int cnt = g_cnt[e];
    int t0 = blockIdx.x * 32;
    if (t0 >= cnt) return;
    int h0 = blockIdx.y * 128;

    __shared__ char smem[3 * MOE_STAGE];
    __shared__ int stok[32];
    __shared__ float swt[32];
    int tid = threadIdx.x, lane = tid & 31, wid = tid >> 5;
    if (tid < 32) {
        int p = t0 + tid;
        if (p < cnt) { stok[tid] = g_list[e * T_TOK + p]; swt[tid] = g_wlist[e * T_TOK + p]; }
        else { stok[tid] = -1; swt[tid] = 0.f; }
    }
    __syncthreads();

    int wm = (wid & 1) * 16;
    int wn = (wid >> 1) * 64;
    float acc[8][4];
#pragma unroll
    for (int a = 0; a < 8; a++)
#pragma unroll
        for (int b = 0; b < 4; b++) acc[a][b] = 0.f;

    const __half* gsrc = g_gh + (size_t)e * T_TOK * I_DIM;
    const __half* wsrc = g_euw_h + (size_t)e * H_DIM * I_DIM;

    auto load_tile = [&](int s, int kb) {
        int ka = kb * 32;
        char* sX = smem + s * MOE_STAGE;
        char* sW = sX + MOE_X_BYTES;
        {
            int r = tid >> 2, c = tid & 3;
            const __half* gx = gsrc + (size_t)(t0 + r) * I_DIM + ka + c * 8;
            uint32_t dx = (uint32_t)__cvta_generic_to_shared(sX + r * 80 + c * 16);
            asm volatile("cp.async.cg.shared.global [%0], [%1], 16;\n" :: "r"(dx), "l"(gx));
        }
#pragma unroll
        for (int i = 0; i < 4; i++) {
            int q = tid + i * 128;
            int r = q >> 2, c = q & 3;
            const __half* gw = wsrc + (size_t)(h0 + r) * I_DIM + ka + c * 8;
            uint32_t dw = (uint32_t)__cvta_generic_to_shared(sW + r * 80 + c * 16);
            asm volatile("cp.async.cg.shared.global [%0], [%1], 16;\n" :: "r"(dw), "l"(gw));
        }
    };

    load_tile(0, 0);
    asm volatile("cp.async.commit_group;\n");
    load_tile(1, 1);
    asm volatile("cp.async.commit_group;\n");

    for (int kb = 0; kb < 4; kb++) {
        int s = kb % 3;
        asm volatile("cp.async.wait_group 1;\n");
        __syncthreads();
        if (kb + 2 < 4) load_tile((kb + 2) % 3, kb + 2);
        asm volatile("cp.async.commit_group;\n");

        uint32_t x_base = (uint32_t)__cvta_generic_to_shared(smem + s * MOE_STAGE);
        uint32_t w_base = x_base + MOE_X_BYTES;
#pragma unroll
        for (int kf = 0; kf < 2; kf++) {
            uint32_t ar[4], br[8][2];
            {
                int m = wm + (lane & 15);
                int k = kf * 16 + (lane >> 4) * 8;
                uint32_t addr = x_base + (uint32_t)(m * MOE_LDA + k) * 2;
                asm volatile("ldmatrix.sync.aligned.m8n8.x4.shared.b16 {%0,%1,%2,%3}, [%4];\n"
                    : "=r"(ar[0]), "=r"(ar[1]), "=r"(ar[2]), "=r"(ar[3]) : "r"(addr));
            }
#pragma unroll
            for (int np = 0; np < 4; np++) {
                int n = wn + np * 16 + (lane >> 4) * 8 + (lane & 7);
                int k = kf * 16 + ((lane >> 3) & 1) * 8;
                uint32_t addr = w_base + (uint32_t)(n * MOE_LDA + k) * 2;
                uint32_t r0, r1, r2, r3;
                asm volatile("ldmatrix.sync.aligned.m8n8.x4.shared.b16 {%0,%1,%2,%3}, [%4];\n"
                    : "=r"(r0), "=r"(r1), "=r"(r2), "=r"(r3) : "r"(addr));
                br[np * 2][0] = r0; br[np * 2][1] = r1;
                br[np * 2 + 1][0] = r2; br[np * 2 + 1][1] = r3;
            }
#pragma unroll
            for (int nf = 0; nf < 8; nf++) {
                float* c = acc[nf];
                asm volatile(
                    "mma.sync.aligned.m16n8k16.row.col.f32.f16.f16.f32 "
                    "{%0,%1,%2,%3}, {%4,%5,%6,%7}, {%8,%9}, {%0,%1,%2,%3};\n"
                    : "+f"(c[0]), "+f"(c[1]), "+f"(c[2]), "+f"(c[3])
                    : "r"(ar[0]), "r"(ar[1]), "r"(ar[2]), "r"(ar[3]),
                      "r"(br[nf][0]), "r"(br[nf][1]));
            }
        }
        __syncthreads();
    }

    int g = lane >> 2, tq = lane & 3;
    int row0 = wm + g, row1 = wm + g + 8;
    int tok0 = stok[row0], tok1 = stok[row1];
    float w0 = swt[row0], w1 = swt[row1];
#pragma unroll
    for (int nf = 0; nf < 8; nf++) {
        int col = h0 + wn + nf * 8 + tq * 2;
        float b0 = eub[e * H_DIM + col], b1 = eub[e * H_DIM + col + 1];
        if (tok0 >= 0) {
            atomicAdd(&g_moe[(size_t)tok0 * H_DIM + col],     w0 * (acc[nf][0] + b0));
            atomicAdd(&g_moe[(size_t)tok0 * H_DIM + col + 1], w0 * (acc[nf][1] + b1));
        }
        if (tok1 >= 0) {
            atomicAdd(&g_moe[(size_t)tok1 * H_DIM + col],     w1 * (acc[nf][2] + b0));
            atomicAdd(&g_moe[(size_t)tok1 * H_DIM + col + 1], w1 * (acc[nf][3] + b1));
        }
    }
}

// ------------------- RMSNorm2 + fp16 A' build (K=1024) -------------------
__global__ __launch_bounds__(256) void rms2_split_kernel(const float* __restrict__ n2w)
{
    int t = blockIdx.x;
    int tid = threadIdx.x, lane = tid & 31, wid = tid >> 5;
    __shared__ float red[8];
    __shared__ float sinv;
    float pre[4]; float ssq = 0.f;
#pragma unroll
    for (int c = 0; c < 4; c++) {
        int h = c * 256 + tid;
        float p = g_x1[(size_t)t * H_DIM + h] + g_moe[(size_t)t * H_DIM + h];
        pre[c] = p; ssq += p * p;
    }
#pragma unroll
    for (int o = 16; o; o >>= 1) ssq += __shfl_xor_sync(0xffffffffu, ssq, o);
    if (lane == 0) red[wid] = ssq;
    __syncthreads();
    if (tid == 0) {
        float s = 0.f;
        for (int w = 0; w < 8; w++) s += red[w];
        sinv = rsqrtf(s * (1.f / H_DIM) + EPSF);
    }
    __syncthreads();
    float inv = sinv;
#pragma unroll
    for (int c = 0; c < 4; c++) {
        int h = c * 256 + tid;
        float v = pre[c] * inv * n2w[h];
        g_Ap[(size_t)t * H_DIM + h] = __float2half(v);
    }
}

// ------------------- head_w -> fp16 -------------------
__global__ __launch_bounds__(256) void wconv_kernel(const float* __restrict__ w)
{
    size_t i = ((size_t)blockIdx.x * 256 + threadIdx.x) * 8;
    float4 v0 = *(const float4*)(w + i);
    float4 v1 = *(const float4*)(w + i + 4);
    __half2 h0 = __floats2half2_rn(v0.x, v0.y);
    __half2 h1 = __floats2half2_rn(v0.z, v0.w);
    __half2 h2 = __floats2half2_rn(v1.x, v1.y);
    __half2 h3 = __floats2half2_rn(v1.z, v1.w);
    uint4 pk;
    pk.x = *(uint32_t*)&h0; pk.y = *(uint32_t*)&h1;
    pk.z = *(uint32_t*)&h2; pk.w = *(uint32_t*)&h3;
    *(uint4*)(g_Wh + i) = pk;
}

// ------------------- head GEMM: out[4096,32000] = Ap[4096,1024] @ Wh[32000,1024]^T
// 128x256 CTA tile, BK=64 (R15 proven), 3-stage cp.async ring.
#define LDA_S 72                       // 64 halves + 8 pad = 144B rows; 9m mod 8 bijective
#define HG_A_BYTES (128 * LDA_S * 2)   // 18432
#define HG_B_BYTES (256 * LDA_S * 2)   // 36864
#define HG_STAGE_BYTES (HG_A_BYTES + HG_B_BYTES)   // 55296
#define HG_STAGES 3
#define HG_KB 16
#define HG_SMEM (HG_STAGES * HG_STAGE_BYTES)       // 165888

__global__ __launch_bounds__(256, 1) void head_gemm_kernel(float* __restrict__ out)
{
    char* smem = dyn_smem;

    int bid = blockIdx.x;
    const int GROUP = 16;
    int group = bid / (GROUP * 125);
    int rem = bid % (GROUP * 125);
    int bm = group * GROUP + (rem % GROUP);
    int bn = rem / GROUP;
    int m0 = bm * 128, n0 = bn * 256;

    int tid = threadIdx.x;
    int lane = tid & 31, wid = tid >> 5;
    int wm = (wid & 1) * 64;
    int wn = (wid >> 1) * 64;

    float acc[4][8][4];
#pragma unroll
    for (int a = 0; a < 4; a++)
#pragma unroll
        for (int b = 0; b < 8; b++)
#pragma unroll
            for (int c = 0; c < 4; c++) acc[a][b][c] = 0.f;

    auto load_tile = [&](int s, int kb) {
        int ka = kb * 64;
        char* sA = smem + s * HG_STAGE_BYTES;
        char* sB = sA + HG_A_BYTES;
#pragma unroll
        for (int i = 0; i < 4; i++) {
            int q = tid + i * 256;
            int r = q >> 3, c = q & 7;
            const __half* ga = g_Ap + (size_t)(m0 + r) * H_DIM + ka + c * 8;
            uint32_t da = (uint32_t)__cvta_generic_to_shared(sA + r * 144 + c * 16);
            asm volatile("cp.async.cg.shared.global [%0], [%1], 16;\n" :: "r"(da), "l"(ga));
        }
#pragma unroll
        for (int i = 0; i < 8; i++) {
            int q = tid + i * 256;
            int r = q >> 3, c = q & 7;
            const __half* gb = g_Wh + (size_t)(n0 + r) * H_DIM + ka + c * 8;
            uint32_t db = (uint32_t)__cvta_generic_to_shared(sB + r * 144 + c * 16);
            asm volatile("cp.async.cg.shared.global [%0], [%1], 16;\n" :: "r"(db), "l"(gb));
        }
    };

    load_tile(0, 0);
    asm volatile("cp.async.commit_group;\n");
    load_tile(1, 1);
    asm volatile("cp.async.commit_group;\n");

    for (int kb = 0; kb < HG_KB; kb++) {
        int s = kb % HG_STAGES;
        asm volatile("cp.async.wait_group 1;\n");
        __syncthreads();

        if (kb + 2 < HG_KB) load_tile((kb + 2) % HG_STAGES, kb + 2);
        asm volatile("cp.async.commit_group;\n");

        uint32_t a_base = (uint32_t)__cvta_generic_to_shared(smem + s * HG_STAGE_BYTES);
        uint32_t b_base = a_base + HG_A_BYTES;
#pragma unroll
        for (int kf = 0; kf < 4; kf++) {
            uint32_t ar[4][4], br[8][2];
#pragma unroll
            for (int mf = 0; mf < 4; mf++) {
                int m = wm + mf * 16 + (lane & 15);
                int k = kf * 16 + (lane >> 4) * 8;
                uint32_t addr = a_base + (uint32_t)(m * LDA_S + k) * 2;
                asm volatile("ldmatrix.sync.aligned.m8n8.x4.shared.b16 {%0,%1,%2,%3}, [%4];\n"
                    : "=r"(ar[mf][0]), "=r"(ar[mf][1]), "=r"(ar[mf][2]), "=r"(ar[mf][3])
                    : "r"(addr));
            }
#pragma unroll
            for (int np = 0; np < 4; np++) {
                int n = wn + np * 16 + (lane >> 4) * 8 + (lane & 7);
                int k = kf * 16 + ((lane >> 3) & 1) * 8;
                uint32_t addr = b_base + (uint32_t)(n * LDA_S + k) * 2;
                uint32_t r0, r1, r2, r3;
                asm volatile("ldmatrix.sync.aligned.m8n8.x4.shared.b16 {%0,%1,%2,%3}, [%4];\n"
                    : "=r"(r0), "=r"(r1), "=r"(r2), "=r"(r3) : "r"(addr));
                br[np * 2][0] = r0; br[np * 2][1] = r1;
                br[np * 2 + 1][0] = r2; br[np * 2 + 1][1] = r3;
            }
#pragma unroll
            for (int mf = 0; mf < 4; mf++)
#pragma unroll
                for (int nf = 0; nf < 8; nf++) {
                    float* c = acc[mf][nf];
                    asm volatile(
                        "mma.sync.aligned.m16n8k16.row.col.f32.f16.f16.f32 "
                        "{%0,%1,%2,%3}, {%4,%5,%6,%7}, {%8,%9}, {%0,%1,%2,%3};\n"
                        : "+f"(c[0]), "+f"(c[1]), "+f"(c[2]), "+f"(c[3])
                        : "r"(ar[mf][0]), "r"(ar[mf][1]), "r"(ar[mf][2]), "r"(ar[mf][3]),
                          "r"(br[nf][0]), "r"(br[nf][1]));
                }
        }
    }

    int g = lane >> 2, tq = lane & 3;
#pragma unroll
    for (int mf = 0; mf < 4; mf++) {
#pragma unroll
        for (int nf = 0; nf < 8; nf++) {
            int row = m0 + wm + mf * 16 + g;
            int col = n0 + wn + nf * 8 + tq * 2;
            *(float2*)&out[(size_t)row * V_DIM + col] =
                make_float2(acc[mf][nf][0], acc[mf][nf][1]);
            *(float2*)&out[(size_t)(row + 8) * V_DIM + col] =
                make_float2(acc[mf][nf][2], acc[mf][nf][3]);
        }
    }
}

// ------------------- launch -------------------
extern "C" void kernel_launch(void* const* d_in, const int* in_sizes, int n_in,
                              void* d_out, int out_size)
{
    const float* x    = (const float*)d_in[0];
    const float* qA   = (const float*)d_in[1];
    const float* qB   = (const float*)d_in[2];
    const float* kA   = (const float*)d_in[3];
    const float* kB   = (const float*)d_in[4];
    const float* vA   = (const float*)d_in[5];
    const float* vB   = (const float*)d_in[6];
    const float* oA   = (const float*)d_in[7];
    const float* oB   = (const float*)d_in[8];
    const float* n1w  = (const float*)d_in[9];
    const float* n2w  = (const float*)d_in[10];
    const float* rw   = (const float*)d_in[11];
    const float* egw  = (const float*)d_in[12];
    const float* egb  = (const float*)d_in[13];
    const float* euw  = (const float*)d_in[14];
    const float* eub  = (const float*)d_in[15];
    const float* hw   = (const float*)d_in[16];
    float* out = (float*)d_out;

    static bool attr_set = false;
    if (!attr_set) {
        cudaFuncSetAttribute(head_gemm_kernel,
                             cudaFuncAttributeMaxDynamicSharedMemorySize, HG_SMEM);
        cudaFuncSetAttribute(lora_rms1_kernel,
                             cudaFuncAttributeMaxDynamicSharedMemorySize, LORA_SMEM);
        attr_set = true;
    }

    loraconv_kernel<<<32, 256>>>(qA, qB, kA, kB, vA, vB, oA, oB);
    lora_rms1_kernel<<<512, 256, LORA_SMEM>>>(x, n1w);
    router_kernel<<<512, 256>>>(rw);
    moeconv_kernel<<<1024, 256>>>(egw, euw);
    gate_mma_kernel<<<dim3(128, 8), 128>>>(egb);
    up_mma_kernel<<<dim3(128, 8, 8), 128>>>(eub);
    rms2_split_kernel<<<4096, 256>>>(n2w);
    wconv_kernel<<<16000, 256>>>(hw);
    head_gemm_kernel<<<4000, 256, HG_SMEM>>>(out);
}